// round 7
// baseline (speedup 1.0000x reference)
#include <cuda_runtime.h>

// x:(T,B,NI) W1:(NH,NI) b1:(NH) W2:(NO,NH) b2:(NO)
// out = concat(spk1[T,B,NH], mem1[T,B,NH], spk2[T,B,NO], mem2[T,B,NO])
#define T_STEPS 100
#define BATCH   65536
#define NI      2
#define NH      10
#define NO      4
#define NHH     5      // hidden units per lane (NH/2)
#define BETA    0.5f
#define THRV    1.0f

#define BLOCK_THREADS 64
#define BATCH_PER_BLOCK (BLOCK_THREADS / 2)   // 32

// smem staging (floats), b-major matching global layout:
#define SPK1_OFF 0
#define MEM1_OFF (BATCH_PER_BLOCK * NH)                            // 320
#define SPK2_OFF (2 * BATCH_PER_BLOCK * NH)                        // 640
#define MEM2_OFF (2 * BATCH_PER_BLOCK * NH + BATCH_PER_BLOCK * NO) // 768
#define BUF_FLOATS (BATCH_PER_BLOCK * (2 * NH + 2 * NO))           // 896

__global__ __launch_bounds__(BLOCK_THREADS, 14) void snn_kernel(
    const float* __restrict__ x,
    const float* __restrict__ W1,
    const float* __restrict__ b1,
    const float* __restrict__ W2,
    const float* __restrict__ b2,
    float* __restrict__ out)
{
    __shared__ float sbuf[2][BUF_FLOATS];

    const int tid  = threadIdx.x;
    const int half = tid & 1;          // 0: h 0-4, o 0-1 ; 1: h 5-9, o 2-3
    const int l    = tid >> 1;         // local batch index 0..31
    const int b0   = blockIdx.x * BATCH_PER_BLOCK;
    const int b    = b0 + l;

    // ---- per-lane weight slices ----
    float w1a[NHH], w1b[NHH], bb1[NHH];
#pragma unroll
    for (int j = 0; j < NHH; j++) {
        const int h = half * NHH + j;
        w1a[j] = __ldg(W1 + h * NI + 0);
        w1b[j] = __ldg(W1 + h * NI + 1);
        bb1[j] = __ldg(b1 + h);
    }
    float w2p[NO][NHH];
#pragma unroll
    for (int o = 0; o < NO; o++)
#pragma unroll
        for (int j = 0; j < NHH; j++)
            w2p[o][j] = __ldg(W2 + o * NH + half * NHH + j);
    float bb2own[2];
    bb2own[0] = __ldg(b2 + half * 2 + 0);
    bb2own[1] = __ldg(b2 + half * 2 + 1);

    // ---- state (per-lane slices) ----
    float mem1[NHH];
    float mem2[2];
#pragma unroll
    for (int j = 0; j < NHH; j++) mem1[j] = 0.0f;
    mem2[0] = 0.0f; mem2[1] = 0.0f;

    // ---- output bases ----
    float* const oSpk1 = out;
    float* const oMem1 = out + (size_t)T_STEPS * BATCH * NH;
    float* const oSpk2 = out + (size_t)2 * T_STEPS * BATCH * NH;
    float* const oMem2 = oSpk2 + (size_t)T_STEPS * BATCH * NO;

    const float2* __restrict__ xp = reinterpret_cast<const float2*>(x);

    // 2-deep x prefetch (pair lanes load same address -> broadcast)
    float2 xv  = __ldg(&xp[(size_t)0 * BATCH + b]);
    float2 xv1 = __ldg(&xp[(size_t)1 * BATCH + b]);

    for (int t = 0; t < T_STEPS; t++) {
        float2 xnext;
        if (t + 2 < T_STEPS) xnext = __ldg(&xp[(size_t)(t + 2) * BATCH + b]);
        else                 xnext = make_float2(0.0f, 0.0f);

        const float x0 = xv.x, x1 = xv.y;
        float* const buf = sbuf[t & 1];

        // ---- layer 1 LIF (this lane's 5 hidden units) -> smem ----
        float spk1[NHH];
#pragma unroll
        for (int j = 0; j < NHH; j++) {
            float syn   = fmaf(x0, w1a[j], fmaf(x1, w1b[j], bb1[j]));
            float reset = (mem1[j] > THRV) ? THRV : 0.0f;
            float m     = fmaf(BETA, mem1[j], syn) - reset;
            mem1[j]     = m;
            spk1[j]     = (m > THRV) ? 1.0f : 0.0f;
            // stride-5 float addresses: conflict-free STS.32
            buf[SPK1_OFF + l * NH + half * NHH + j] = spk1[j];
            buf[MEM1_OFF + l * NH + half * NHH + j] = m;
        }

        // ---- layer 2: partial sums over local h, combine via shfl ----
        float p[NO];
#pragma unroll
        for (int o = 0; o < NO; o++) {
            float s = 0.0f;
#pragma unroll
            for (int j = 0; j < NHH; j++) s = fmaf(spk1[j], w2p[o][j], s);
            p[o] = s;
        }
        float q[NO];
#pragma unroll
        for (int o = 0; o < NO; o++) q[o] = __shfl_xor_sync(0xFFFFFFFFu, p[o], 1);
        // owned outputs: o = half*2 + {0,1}
#pragma unroll
        for (int k = 0; k < 2; k++) {
            const int o = half * 2 + k;
            float syn   = bb2own[k] + p[o] + q[o];
            float reset = (mem2[k] > THRV) ? THRV : 0.0f;
            float m     = fmaf(BETA, mem2[k], syn) - reset;
            mem2[k]     = m;
            float spk   = (m > THRV) ? 1.0f : 0.0f;
            buf[SPK2_OFF + l * NO + half * 2 + k] = spk;
            buf[MEM2_OFF + l * NO + half * 2 + k] = m;
        }

        __syncthreads();

        // ---- cooperative fully-coalesced streaming stores ----
        {
            const float4* s4 = reinterpret_cast<const float4*>(buf);
            // spk1: 320 floats = 80 f4
            float4* g = reinterpret_cast<float4*>(oSpk1 + (size_t)t * BATCH * NH + (size_t)b0 * NH);
#pragma unroll
            for (int i = tid; i < (BATCH_PER_BLOCK * NH) / 4; i += BLOCK_THREADS)
                __stcs(&g[i], s4[SPK1_OFF / 4 + i]);
            // mem1: 80 f4
            g = reinterpret_cast<float4*>(oMem1 + (size_t)t * BATCH * NH + (size_t)b0 * NH);
#pragma unroll
            for (int i = tid; i < (BATCH_PER_BLOCK * NH) / 4; i += BLOCK_THREADS)
                __stcs(&g[i], s4[MEM1_OFF / 4 + i]);
            // spk2 (32 f4) by threads 0-31, mem2 (32 f4) by threads 32-63
            if (tid < 32) {
                g = reinterpret_cast<float4*>(oSpk2 + (size_t)t * BATCH * NO + (size_t)b0 * NO);
                __stcs(&g[tid], s4[SPK2_OFF / 4 + tid]);
            } else {
                g = reinterpret_cast<float4*>(oMem2 + (size_t)t * BATCH * NO + (size_t)b0 * NO);
                __stcs(&g[tid - 32], s4[MEM2_OFF / 4 + (tid - 32)]);
            }
        }

        xv  = xv1;
        xv1 = xnext;
    }
}

extern "C" void kernel_launch(void* const* d_in, const int* in_sizes, int n_in,
                              void* d_out, int out_size) {
    const float* x  = (const float*)d_in[0];
    const float* W1 = (const float*)d_in[1];
    const float* b1 = (const float*)d_in[2];
    const float* W2 = (const float*)d_in[3];
    const float* b2 = (const float*)d_in[4];
    float* out = (float*)d_out;

    snn_kernel<<<BATCH / BATCH_PER_BLOCK, BLOCK_THREADS>>>(x, W1, b1, W2, b2, out);
}

// round 8
// speedup vs baseline: 1.0965x; 1.0965x over previous
#include <cuda_runtime.h>

// x:(T,B,NI) W1:(NH,NI) b1:(NH) W2:(NO,NH) b2:(NO)
// out = concat(spk1[T,B,NH], mem1[T,B,NH], spk2[T,B,NO], mem2[T,B,NO])
#define T_STEPS 100
#define BATCH   65536
#define NI      2
#define NH      10
#define NO      4
#define BETA    0.5f
#define THRV    1.0f

#define BLOCK_THREADS 128

// per-block smem staging regions (in floats) — R2 layout, scaled to 128 threads
#define SPK1_OFF 0
#define MEM1_OFF (BLOCK_THREADS * NH)                           // 1280
#define SPK2_OFF (2 * BLOCK_THREADS * NH)                       // 2560
#define MEM2_OFF (2 * BLOCK_THREADS * NH + BLOCK_THREADS * NO)  // 3072
#define BUF_FLOATS (BLOCK_THREADS * (2 * NH + 2 * NO))          // 3584

__global__ __launch_bounds__(BLOCK_THREADS) void snn_kernel(
    const float* __restrict__ x,
    const float* __restrict__ W1,
    const float* __restrict__ b1,
    const float* __restrict__ W2,
    const float* __restrict__ b2,
    float* __restrict__ out)
{
    __shared__ float sbuf[2][BUF_FLOATS];

    const int tid = threadIdx.x;
    const int b   = blockIdx.x * BLOCK_THREADS + tid;
    const int b0  = blockIdx.x * BLOCK_THREADS;

    // ---- weights into registers ----
    float w1a[NH], w1b[NH], bb1[NH];
#pragma unroll
    for (int h = 0; h < NH; h++) {
        w1a[h] = __ldg(W1 + h * NI + 0);
        w1b[h] = __ldg(W1 + h * NI + 1);
        bb1[h] = __ldg(b1 + h);
    }
    float w2[NO][NH], bb2[NO];
#pragma unroll
    for (int o = 0; o < NO; o++) {
        bb2[o] = __ldg(b2 + o);
#pragma unroll
        for (int h = 0; h < NH; h++) w2[o][h] = __ldg(W2 + o * NH + h);
    }

    // ---- state ----
    float mem1[NH];
    float mem2[NO];
#pragma unroll
    for (int h = 0; h < NH; h++) mem1[h] = 0.0f;
#pragma unroll
    for (int o = 0; o < NO; o++) mem2[o] = 0.0f;

    // ---- output bases ----
    float* const oSpk1 = out;
    float* const oMem1 = out + (size_t)T_STEPS * BATCH * NH;
    float* const oSpk2 = out + (size_t)2 * T_STEPS * BATCH * NH;
    float* const oMem2 = oSpk2 + (size_t)T_STEPS * BATCH * NO;

    const float2* __restrict__ xp = reinterpret_cast<const float2*>(x);

    // 2-deep prefetch pipeline for x
    float2 xv  = __ldg(&xp[(size_t)0 * BATCH + b]);
    float2 xv1 = __ldg(&xp[(size_t)1 * BATCH + b]);

    for (int t = 0; t < T_STEPS; t++) {
        float2 xnext;
        if (t + 2 < T_STEPS) xnext = __ldg(&xp[(size_t)(t + 2) * BATCH + b]);
        else                 xnext = make_float2(0.0f, 0.0f);

        const float x0 = xv.x, x1 = xv.y;
        float* const buf = sbuf[t & 1];

        // ---- layer 1 LIF -> smem ----
        float spk1[NH];
#pragma unroll
        for (int h = 0; h < NH; h++) {
            float syn   = fmaf(x0, w1a[h], fmaf(x1, w1b[h], bb1[h]));
            float reset = (mem1[h] > THRV) ? THRV : 0.0f;
            float m     = fmaf(BETA, mem1[h], syn) - reset;
            mem1[h]     = m;
            spk1[h]     = (m > THRV) ? 1.0f : 0.0f;
        }
        {
            float2* ps = reinterpret_cast<float2*>(buf + SPK1_OFF + tid * NH);
            float2* pm = reinterpret_cast<float2*>(buf + MEM1_OFF + tid * NH);
#pragma unroll
            for (int i = 0; i < NH / 2; i++) {
                ps[i] = make_float2(spk1[2 * i], spk1[2 * i + 1]);
                pm[i] = make_float2(mem1[2 * i], mem1[2 * i + 1]);
            }
        }

        // ---- layer 2 LIF -> smem ----
        float spk2[NO];
#pragma unroll
        for (int o = 0; o < NO; o++) {
            float syn = bb2[o];
#pragma unroll
            for (int h = 0; h < NH; h++) syn = fmaf(spk1[h], w2[o][h], syn);
            float reset = (mem2[o] > THRV) ? THRV : 0.0f;
            float m     = fmaf(BETA, mem2[o], syn) - reset;
            mem2[o]     = m;
            spk2[o]     = (m > THRV) ? 1.0f : 0.0f;
        }
        {
            float4* ps = reinterpret_cast<float4*>(buf + SPK2_OFF + tid * NO);
            float4* pm = reinterpret_cast<float4*>(buf + MEM2_OFF + tid * NO);
            ps[0] = make_float4(spk2[0], spk2[1], spk2[2], spk2[3]);
            pm[0] = make_float4(mem2[0], mem2[1], mem2[2], mem2[3]);
        }

        __syncthreads();

        // ---- cooperative fully-coalesced streaming stores ----
        {
            const float4* s4 = reinterpret_cast<const float4*>(buf);
            // spk1: 1280 floats = 320 float4
            float4* g = reinterpret_cast<float4*>(oSpk1 + (size_t)t * BATCH * NH + (size_t)b0 * NH);
#pragma unroll
            for (int i = tid; i < (BLOCK_THREADS * NH) / 4; i += BLOCK_THREADS)
                __stcs(&g[i], s4[SPK1_OFF / 4 + i]);
            // mem1
            g = reinterpret_cast<float4*>(oMem1 + (size_t)t * BATCH * NH + (size_t)b0 * NH);
#pragma unroll
            for (int i = tid; i < (BLOCK_THREADS * NH) / 4; i += BLOCK_THREADS)
                __stcs(&g[i], s4[MEM1_OFF / 4 + i]);
            // spk2: 512 floats = 128 float4 -> one per thread
            g = reinterpret_cast<float4*>(oSpk2 + (size_t)t * BATCH * NO + (size_t)b0 * NO);
            __stcs(&g[tid], s4[SPK2_OFF / 4 + tid]);
            // mem2
            g = reinterpret_cast<float4*>(oMem2 + (size_t)t * BATCH * NO + (size_t)b0 * NO);
            __stcs(&g[tid], s4[MEM2_OFF / 4 + tid]);
        }

        xv  = xv1;
        xv1 = xnext;
    }
}

extern "C" void kernel_launch(void* const* d_in, const int* in_sizes, int n_in,
                              void* d_out, int out_size) {
    const float* x  = (const float*)d_in[0];
    const float* W1 = (const float*)d_in[1];
    const float* b1 = (const float*)d_in[2];
    const float* W2 = (const float*)d_in[3];
    const float* b2 = (const float*)d_in[4];
    float* out = (float*)d_out;

    snn_kernel<<<BATCH / BLOCK_THREADS, BLOCK_THREADS>>>(x, W1, b1, W2, b2, out);
}